// round 16
// baseline (speedup 1.0000x reference)
#include <cuda_runtime.h>

#define Bv 4
#define Tv 256
#define Ev 512
#define Hv 8
#define Sv 64

typedef unsigned long long u64;

// packed fp32x2 helpers (FFMA2 path — ptxas never emits this from C++)
__device__ __forceinline__ u64 pk2(float x, float y) {
    u64 r; asm("mov.b64 %0,{%1,%2};" : "=l"(r) : "f"(x), "f"(y)); return r;
}
__device__ __forceinline__ void upk2(u64 v, float& x, float& y) {
    asm("mov.b64 {%0,%1},%2;" : "=f"(x), "=f"(y) : "l"(v));
}
__device__ __forceinline__ void fma2(u64& d, u64 a, u64 b) {
    asm("fma.rn.f32x2 %0,%1,%2,%0;" : "+l"(d) : "l"(a), "l"(b));
}
__device__ __forceinline__ u64 add2(u64 a, u64 b) {
    u64 r; asm("add.rn.f32x2 %0,%1,%2;" : "=l"(r) : "l"(a), "l"(b)); return r;
}

// scratch (allocation-free rule: __device__ globals)
__device__ float g_q[Bv*Tv*Ev];
__device__ float g_k[Bv*Tv*Ev];
__device__ float g_v[Bv*Tv*Ev];
__device__ float g_vec[Bv*Tv*Ev];

// ---------------------------------------------------------------------------
// K1: q/k/v projections (R8 exact — best measured 12.8us).
// grid = (16 token-tiles, 8 heads), 256 threads; x tile reused for 3 weights.
// ---------------------------------------------------------------------------
__global__ void __launch_bounds__(256) qkv_kernel(const float* __restrict__ x,
                                                  const float* __restrict__ Wq,
                                                  const float* __restrict__ Wk,
                                                  const float* __restrict__ Wv)
{
    __shared__ float xs[64][68];   // [d][token]
    __shared__ float ws[64][68];   // [d][o]
    const int t0  = blockIdx.x * 64;
    const int n   = blockIdx.y;
    const int tid = threadIdx.x;
    const int ty  = tid >> 4, tx = tid & 15;

    #pragma unroll
    for (int ch = tid; ch < 1024; ch += 256) {
        const int r = ch >> 4, d = (ch & 15) * 4;
        const float4 v4 = *(const float4*)&x[(size_t)(t0 + r)*Ev + n*Sv + d];
        xs[d][r] = v4.x; xs[d+1][r] = v4.y; xs[d+2][r] = v4.z; xs[d+3][r] = v4.w;
    }

    const float* Wlist[3] = {Wq, Wk, Wv};
    float*       Olist[3] = {g_q, g_k, g_v};

    #pragma unroll
    for (int w = 0; w < 3; w++) {
        __syncthreads();
        const float* W = Wlist[w];
        #pragma unroll
        for (int ch = tid; ch < 1024; ch += 256) {
            const int o = ch >> 4, d = (ch & 15) * 4;
            const float4 v4 = *(const float4*)&W[o*Sv + d];
            ws[d][o] = v4.x; ws[d+1][o] = v4.y; ws[d+2][o] = v4.z; ws[d+3][o] = v4.w;
        }
        __syncthreads();

        u64 accp[4][2];
        #pragma unroll
        for (int r = 0; r < 4; r++) { accp[r][0] = pk2(0.f,0.f); accp[r][1] = pk2(0.f,0.f); }

        #pragma unroll 8
        for (int k = 0; k < 64; k++) {
            const float4 a4 = *(const float4*)&xs[k][ty*4];
            const float4 b4 = *(const float4*)&ws[k][tx*4];
            const u64 b01 = pk2(b4.x, b4.y), b23 = pk2(b4.z, b4.w);
            const float a[4] = {a4.x, a4.y, a4.z, a4.w};
            #pragma unroll
            for (int r = 0; r < 4; r++) {
                const u64 aa = pk2(a[r], a[r]);
                fma2(accp[r][0], aa, b01);
                fma2(accp[r][1], aa, b23);
            }
        }

        float* O = Olist[w];
        #pragma unroll
        for (int r = 0; r < 4; r++) {
            float4 o;
            upk2(accp[r][0], o.x, o.y);
            upk2(accp[r][1], o.z, o.w);
            *(float4*)&O[(size_t)(t0 + ty*4 + r)*Ev + n*Sv + tx*4] = o;
        }
    }
}

// ---------------------------------------------------------------------------
// K2: fused attention (R12 exactly — measured ~168us, near DRAM floor).
// ---------------------------------------------------------------------------
__global__ void __launch_bounds__(256) attn_kernel(const float* __restrict__ ek,
                                                   const float* __restrict__ ev,
                                                   const int*   __restrict__ mask)
{
    __shared__ float sc[Hv][Tv];     // scores -> probs
    __shared__ float qsm[Ev];

    const int bi   = blockIdx.x;
    const int b    = bi >> 8;
    const int tid  = threadIdx.x;
    const int warp = tid >> 5;
    const int lane = tid & 31;

    qsm[tid]       = g_q[(size_t)bi*Ev + tid];
    qsm[tid + 256] = g_q[(size_t)bi*Ev + tid + 256];
    __syncthreads();

    const float q0 = qsm[warp*64 + 2*lane];
    const float q1 = qsm[warp*64 + 2*lane + 1];

    const float2* ekp = (const float2*)ek  + (((size_t)bi*Tv*Ev) >> 1) + warp*32 + lane;
    const float2* kp  = (const float2*)g_k + (((size_t)b *Tv*Ev) >> 1) + warp*32 + lane;

    // ---- Pass A: score = q.(k + ek), single shuffle tree ----
    for (int j0 = 0; j0 < Tv; j0 += 8) {
        float2 re[8], rk[8];
        #pragma unroll
        for (int u = 0; u < 8; u++) re[u] = ekp[(size_t)(j0 + u) * 256];
        #pragma unroll
        for (int u = 0; u < 8; u++) rk[u] = kp[(size_t)(j0 + u) * 256];
        #pragma unroll
        for (int u = 0; u < 8; u++) {
            const float sx = re[u].x + rk[u].x;
            const float sy = re[u].y + rk[u].y;
            float p = fmaf(sx, q0, sy * q1);
            p += __shfl_xor_sync(0xffffffffu, p, 16);
            p += __shfl_xor_sync(0xffffffffu, p, 8);
            p += __shfl_xor_sync(0xffffffffu, p, 4);
            p += __shfl_xor_sync(0xffffffffu, p, 2);
            p += __shfl_xor_sync(0xffffffffu, p, 1);
            if (lane == 0) sc[warp][j0 + u] = p;
        }
    }
    __syncwarp();

    // ---- softmax per head (warp-local over 256 j) ----
    const float scale = 0.125f;   // 1/sqrt(64)
    const int* mrow = mask + (size_t)bi * Tv;
    float vbuf[8];
    float mx = -1e30f;
    #pragma unroll
    for (int t = 0; t < 8; t++) {
        const int j = lane + 32*t;
        float s = sc[warp][j];
        s = (mrow[j] == 0) ? -1e9f : s * scale;
        vbuf[t] = s;
        mx = fmaxf(mx, s);
    }
    mx = fmaxf(mx, __shfl_xor_sync(0xffffffffu, mx, 16));
    mx = fmaxf(mx, __shfl_xor_sync(0xffffffffu, mx, 8));
    mx = fmaxf(mx, __shfl_xor_sync(0xffffffffu, mx, 4));
    mx = fmaxf(mx, __shfl_xor_sync(0xffffffffu, mx, 2));
    mx = fmaxf(mx, __shfl_xor_sync(0xffffffffu, mx, 1));
    float sum = 0.f;
    #pragma unroll
    for (int t = 0; t < 8; t++) {
        const float e = expf(vbuf[t] - mx);
        vbuf[t] = e;
        sum += e;
    }
    sum += __shfl_xor_sync(0xffffffffu, sum, 16);
    sum += __shfl_xor_sync(0xffffffffu, sum, 8);
    sum += __shfl_xor_sync(0xffffffffu, sum, 4);
    sum += __shfl_xor_sync(0xffffffffu, sum, 2);
    sum += __shfl_xor_sync(0xffffffffu, sum, 1);
    const float inv = 1.f / sum;
    #pragma unroll
    for (int t = 0; t < 8; t++)
        sc[warp][lane + 32*t] = vbuf[t] * inv;
    __syncwarp();

    // ---- Pass B: stream ev + L2 v, packed accumulate ----
    const float2* evp = (const float2*)ev  + (((size_t)bi*Tv*Ev) >> 1) + warp*32 + lane;
    const float2* vp  = (const float2*)g_v + (((size_t)b *Tv*Ev) >> 1) + warp*32 + lane;
    u64 acc = pk2(0.f, 0.f);
    for (int j0 = 0; j0 < Tv; j0 += 8) {
        float2 re[8], rv[8];
        #pragma unroll
        for (int u = 0; u < 8; u++) re[u] = evp[(size_t)(j0 + u) * 256];
        #pragma unroll
        for (int u = 0; u < 8; u++) rv[u] = vp[(size_t)(j0 + u) * 256];
        #pragma unroll
        for (int u = 0; u < 8; u++) {
            const float p = sc[warp][j0 + u];
            const u64 s = add2(pk2(re[u].x, re[u].y), pk2(rv[u].x, rv[u].y));
            fma2(acc, pk2(p, p), s);
        }
    }
    float a0, a1; upk2(acc, a0, a1);
    g_vec[(size_t)bi*Ev + warp*64 + 2*lane]     = a0;
    g_vec[(size_t)bi*Ev + warp*64 + 2*lane + 1] = a1;
}

// ---------------------------------------------------------------------------
// K3: out = vec @ Wu^T + bu.  BM=64, BN=32, BK=32, now 256 threads (8 warps),
// TM=2 x TN=4, double-buffered, grid (16,16) = 256 CTAs -> ~14 warps/SM.
// ---------------------------------------------------------------------------
__global__ void __launch_bounds__(256) proj_kernel(const float* __restrict__ Wu,
                                                   const float* __restrict__ bu,
                                                   float* __restrict__ out)
{
    __shared__ float As[2][32][68];   // [buf][k][r]
    __shared__ float Bs[2][32][36];   // [buf][k][c]
    const int r0  = blockIdx.x * 64;
    const int c0  = blockIdx.y * 32;
    const int tid = threadIdx.x;
    const int ty  = tid >> 3;       // 0..31 -> rows ty*2..+1
    const int tx  = tid & 7;        // 0..7  -> cols tx*4..+3

    // load assignments: As 512 f4 chunks (2/thread), Bs 256 (1/thread)
    const int ar0 = tid >> 3;              // chunk rows tid>>3 and +32
    const int ak  = (tid & 7) * 4;
    const int bc  = tid >> 3;              // 0..31
    const int bk  = (tid & 7) * 4;

    float4 pa[2], pb;

    pa[0] = *(const float4*)&g_vec[(size_t)(r0 + ar0)*Ev + ak];
    pa[1] = *(const float4*)&g_vec[(size_t)(r0 + ar0 + 32)*Ev + ak];
    pb    = *(const float4*)&Wu[(size_t)(c0 + bc)*Ev + bk];

    #pragma unroll
    for (int i = 0; i < 2; i++) {
        const int r = ar0 + i*32;
        As[0][ak][r] = pa[i].x; As[0][ak+1][r] = pa[i].y;
        As[0][ak+2][r] = pa[i].z; As[0][ak+3][r] = pa[i].w;
    }
    Bs[0][bk][bc] = pb.x; Bs[0][bk+1][bc] = pb.y;
    Bs[0][bk+2][bc] = pb.z; Bs[0][bk+3][bc] = pb.w;
    __syncthreads();

    u64 accp[2][2];
    accp[0][0] = pk2(0.f,0.f); accp[0][1] = pk2(0.f,0.f);
    accp[1][0] = pk2(0.f,0.f); accp[1][1] = pk2(0.f,0.f);

    for (int t = 0; t < 16; t++) {
        const int cur = t & 1, nxt = cur ^ 1;

        if (t < 15) {
            const int k0 = (t + 1) * 32;
            pa[0] = *(const float4*)&g_vec[(size_t)(r0 + ar0)*Ev + k0 + ak];
            pa[1] = *(const float4*)&g_vec[(size_t)(r0 + ar0 + 32)*Ev + k0 + ak];
            pb    = *(const float4*)&Wu[(size_t)(c0 + bc)*Ev + k0 + bk];
        }

        #pragma unroll 8
        for (int k = 0; k < 32; k++) {
            const float2 a2 = *(const float2*)&As[cur][k][ty*2];
            const float4 b4 = *(const float4*)&Bs[cur][k][tx*4];
            const u64 b01 = pk2(b4.x, b4.y), b23 = pk2(b4.z, b4.w);
            const u64 aa0 = pk2(a2.x, a2.x);
            const u64 aa1 = pk2(a2.y, a2.y);
            fma2(accp[0][0], aa0, b01);
            fma2(accp[0][1], aa0, b23);
            fma2(accp[1][0], aa1, b01);
            fma2(accp[1][1], aa1, b23);
        }

        if (t < 15) {
            #pragma unroll
            for (int i = 0; i < 2; i++) {
                const int r = ar0 + i*32;
                As[nxt][ak][r] = pa[i].x; As[nxt][ak+1][r] = pa[i].y;
                As[nxt][ak+2][r] = pa[i].z; As[nxt][ak+3][r] = pa[i].w;
            }
            Bs[nxt][bk][bc] = pb.x; Bs[nxt][bk+1][bc] = pb.y;
            Bs[nxt][bk+2][bc] = pb.z; Bs[nxt][bk+3][bc] = pb.w;
            __syncthreads();
        }
    }

    const float4 bias = *(const float4*)&bu[c0 + tx*4];
    #pragma unroll
    for (int ry = 0; ry < 2; ry++) {
        float4 o;
        upk2(accp[ry][0], o.x, o.y);
        upk2(accp[ry][1], o.z, o.w);
        o.x += bias.x; o.y += bias.y; o.z += bias.z; o.w += bias.w;
        *(float4*)&out[(size_t)(r0 + ty*2 + ry)*Ev + c0 + tx*4] = o;
    }
}

// ---------------------------------------------------------------------------
extern "C" void kernel_launch(void* const* d_in, const int* in_sizes, int n_in,
                              void* d_out, int out_size)
{
    const float* x   = (const float*)d_in[0];
    const float* rk  = (const float*)d_in[1];
    const float* rv  = (const float*)d_in[2];
    const int*   msk = (const int*)  d_in[3];
    const float* Wq  = (const float*)d_in[4];
    const float* Wk  = (const float*)d_in[5];
    const float* Wv  = (const float*)d_in[6];
    const float* Wu  = (const float*)d_in[7];
    const float* bu  = (const float*)d_in[8];
    float* out = (float*)d_out;

    qkv_kernel<<<dim3(16, Hv), 256>>>(x, Wq, Wk, Wv);
    attn_kernel<<<Bv*Tv, 256>>>(rk, rv, msk);
    proj_kernel<<<dim3(16, 16), 256>>>(Wu, bu, out);
}

// round 17
// speedup vs baseline: 1.0727x; 1.0727x over previous
#include <cuda_runtime.h>

#define Bv 4
#define Tv 256
#define Ev 512
#define Hv 8
#define Sv 64

typedef unsigned long long u64;

// packed fp32x2 helpers (FFMA2 path — ptxas never emits this from C++)
__device__ __forceinline__ u64 pk2(float x, float y) {
    u64 r; asm("mov.b64 %0,{%1,%2};" : "=l"(r) : "f"(x), "f"(y)); return r;
}
__device__ __forceinline__ void upk2(u64 v, float& x, float& y) {
    asm("mov.b64 {%0,%1},%2;" : "=f"(x), "=f"(y) : "l"(v));
}
__device__ __forceinline__ void fma2(u64& d, u64 a, u64 b) {
    asm("fma.rn.f32x2 %0,%1,%2,%0;" : "+l"(d) : "l"(a), "l"(b));
}
__device__ __forceinline__ u64 add2(u64 a, u64 b) {
    u64 r; asm("add.rn.f32x2 %0,%1,%2;" : "=l"(r) : "l"(a), "l"(b)); return r;
}

// scratch (allocation-free rule: __device__ globals)
__device__ float g_q[Bv*Tv*Ev];
__device__ float g_k[Bv*Tv*Ev];
__device__ float g_v[Bv*Tv*Ev];
__device__ float g_vec[Bv*Tv*Ev];

// ---------------------------------------------------------------------------
// K1: q/k/v projections (R8 exact — best measured 12.8us).
// ---------------------------------------------------------------------------
__global__ void __launch_bounds__(256) qkv_kernel(const float* __restrict__ x,
                                                  const float* __restrict__ Wq,
                                                  const float* __restrict__ Wk,
                                                  const float* __restrict__ Wv)
{
    __shared__ float xs[64][68];   // [d][token]
    __shared__ float ws[64][68];   // [d][o]
    const int t0  = blockIdx.x * 64;
    const int n   = blockIdx.y;
    const int tid = threadIdx.x;
    const int ty  = tid >> 4, tx = tid & 15;

    #pragma unroll
    for (int ch = tid; ch < 1024; ch += 256) {
        const int r = ch >> 4, d = (ch & 15) * 4;
        const float4 v4 = *(const float4*)&x[(size_t)(t0 + r)*Ev + n*Sv + d];
        xs[d][r] = v4.x; xs[d+1][r] = v4.y; xs[d+2][r] = v4.z; xs[d+3][r] = v4.w;
    }

    const float* Wlist[3] = {Wq, Wk, Wv};
    float*       Olist[3] = {g_q, g_k, g_v};

    #pragma unroll
    for (int w = 0; w < 3; w++) {
        __syncthreads();
        const float* W = Wlist[w];
        #pragma unroll
        for (int ch = tid; ch < 1024; ch += 256) {
            const int o = ch >> 4, d = (ch & 15) * 4;
            const float4 v4 = *(const float4*)&W[o*Sv + d];
            ws[d][o] = v4.x; ws[d+1][o] = v4.y; ws[d+2][o] = v4.z; ws[d+3][o] = v4.w;
        }
        __syncthreads();

        u64 accp[4][2];
        #pragma unroll
        for (int r = 0; r < 4; r++) { accp[r][0] = pk2(0.f,0.f); accp[r][1] = pk2(0.f,0.f); }

        #pragma unroll 8
        for (int k = 0; k < 64; k++) {
            const float4 a4 = *(const float4*)&xs[k][ty*4];
            const float4 b4 = *(const float4*)&ws[k][tx*4];
            const u64 b01 = pk2(b4.x, b4.y), b23 = pk2(b4.z, b4.w);
            const float a[4] = {a4.x, a4.y, a4.z, a4.w};
            #pragma unroll
            for (int r = 0; r < 4; r++) {
                const u64 aa = pk2(a[r], a[r]);
                fma2(accp[r][0], aa, b01);
                fma2(accp[r][1], aa, b23);
            }
        }

        float* O = Olist[w];
        #pragma unroll
        for (int r = 0; r < 4; r++) {
            float4 o;
            upk2(accp[r][0], o.x, o.y);
            upk2(accp[r][1], o.z, o.w);
            *(float4*)&O[(size_t)(t0 + ty*4 + r)*Ev + n*Sv + tx*4] = o;
        }
    }
}

// ---------------------------------------------------------------------------
// K2: fused attention (R12 structure; Pass A reduction replaced by a
// multi-value butterfly fold: 9 shuffles per 8 j's instead of 40).
// ---------------------------------------------------------------------------
__global__ void __launch_bounds__(256) attn_kernel(const float* __restrict__ ek,
                                                   const float* __restrict__ ev,
                                                   const int*   __restrict__ mask)
{
    __shared__ float sc[Hv][Tv];     // scores -> probs
    __shared__ float qsm[Ev];

    const int bi   = blockIdx.x;
    const int b    = bi >> 8;
    const int tid  = threadIdx.x;
    const int warp = tid >> 5;
    const int lane = tid & 31;
    const unsigned FULL = 0xffffffffu;

    qsm[tid]       = g_q[(size_t)bi*Ev + tid];
    qsm[tid + 256] = g_q[(size_t)bi*Ev + tid + 256];
    __syncthreads();

    const float q0 = qsm[warp*64 + 2*lane];
    const float q1 = qsm[warp*64 + 2*lane + 1];

    const float2* ekp = (const float2*)ek  + (((size_t)bi*Tv*Ev) >> 1) + warp*32 + lane;
    const float2* kp  = (const float2*)g_k + (((size_t)b *Tv*Ev) >> 1) + warp*32 + lane;

    const bool h0 = (lane & 1) != 0;
    const bool h1 = (lane & 2) != 0;
    const bool h2 = (lane & 4) != 0;

    // ---- Pass A: score = q.(k + ek); butterfly fold of 8 partials ----
    for (int j0 = 0; j0 < Tv; j0 += 8) {
        float2 re[8], rk[8];
        #pragma unroll
        for (int u = 0; u < 8; u++) re[u] = ekp[(size_t)(j0 + u) * 256];
        #pragma unroll
        for (int u = 0; u < 8; u++) rk[u] = kp[(size_t)(j0 + u) * 256];
        float p[8];
        #pragma unroll
        for (int u = 0; u < 8; u++) {
            const float sx = re[u].x + rk[u].x;
            const float sy = re[u].y + rk[u].y;
            p[u] = fmaf(sx, q0, sy * q1);
        }
        // level 1 (lane bit0 <-> u bit0): 8 -> 4 values, 4 shuffles
        float t[4];
        #pragma unroll
        for (int i = 0; i < 4; i++) {
            const float send = h0 ? p[2*i] : p[2*i+1];
            const float sh = __shfl_xor_sync(FULL, send, 1);
            t[i] = (h0 ? p[2*i+1] : p[2*i]) + sh;
        }
        // level 2: 4 -> 2, 2 shuffles
        float s[2];
        #pragma unroll
        for (int i = 0; i < 2; i++) {
            const float send = h1 ? t[2*i] : t[2*i+1];
            const float sh = __shfl_xor_sync(FULL, send, 2);
            s[i] = (h1 ? t[2*i+1] : t[2*i]) + sh;
        }
        // level 4: 2 -> 1, 1 shuffle
        float r;
        {
            const float send = h2 ? s[0] : s[1];
            const float sh = __shfl_xor_sync(FULL, send, 4);
            r = (h2 ? s[1] : s[0]) + sh;
        }
        // finish lane reduction over bits 3,4
        r += __shfl_xor_sync(FULL, r, 8);
        r += __shfl_xor_sync(FULL, r, 16);
        // lane l (l<8) holds the full sum for u = l
        if (lane < 8) sc[warp][j0 + lane] = r;
    }
    __syncwarp();

    // ---- softmax per head (warp-local over 256 j) ----
    const float scale = 0.125f;   // 1/sqrt(64)
    const int* mrow = mask + (size_t)bi * Tv;
    float vbuf[8];
    float mx = -1e30f;
    #pragma unroll
    for (int t = 0; t < 8; t++) {
        const int j = lane + 32*t;
        float s = sc[warp][j];
        s = (mrow[j] == 0) ? -1e9f : s * scale;
        vbuf[t] = s;
        mx = fmaxf(mx, s);
    }
    mx = fmaxf(mx, __shfl_xor_sync(FULL, mx, 16));
    mx = fmaxf(mx, __shfl_xor_sync(FULL, mx, 8));
    mx = fmaxf(mx, __shfl_xor_sync(FULL, mx, 4));
    mx = fmaxf(mx, __shfl_xor_sync(FULL, mx, 2));
    mx = fmaxf(mx, __shfl_xor_sync(FULL, mx, 1));
    float sum = 0.f;
    #pragma unroll
    for (int t = 0; t < 8; t++) {
        const float e = expf(vbuf[t] - mx);
        vbuf[t] = e;
        sum += e;
    }
    sum += __shfl_xor_sync(FULL, sum, 16);
    sum += __shfl_xor_sync(FULL, sum, 8);
    sum += __shfl_xor_sync(FULL, sum, 4);
    sum += __shfl_xor_sync(FULL, sum, 2);
    sum += __shfl_xor_sync(FULL, sum, 1);
    const float inv = 1.f / sum;
    #pragma unroll
    for (int t = 0; t < 8; t++)
        sc[warp][lane + 32*t] = vbuf[t] * inv;
    __syncwarp();

    // ---- Pass B: stream ev + L2 v, packed accumulate ----
    const float2* evp = (const float2*)ev  + (((size_t)bi*Tv*Ev) >> 1) + warp*32 + lane;
    const float2* vp  = (const float2*)g_v + (((size_t)b *Tv*Ev) >> 1) + warp*32 + lane;
    u64 acc = pk2(0.f, 0.f);
    for (int j0 = 0; j0 < Tv; j0 += 8) {
        float2 re[8], rv[8];
        #pragma unroll
        for (int u = 0; u < 8; u++) re[u] = evp[(size_t)(j0 + u) * 256];
        #pragma unroll
        for (int u = 0; u < 8; u++) rv[u] = vp[(size_t)(j0 + u) * 256];
        #pragma unroll
        for (int u = 0; u < 8; u++) {
            const float p = sc[warp][j0 + u];
            const u64 s = add2(pk2(re[u].x, re[u].y), pk2(rv[u].x, rv[u].y));
            fma2(acc, pk2(p, p), s);
        }
    }
    float a0, a1; upk2(acc, a0, a1);
    g_vec[(size_t)bi*Ev + warp*64 + 2*lane]     = a0;
    g_vec[(size_t)bi*Ev + warp*64 + 2*lane + 1] = a1;
}

// ---------------------------------------------------------------------------
// K3: out = vec @ Wu^T + bu (R12 exact — best measured ~28us).
// BM=64, BN=32, BK=32, 128 threads, grid (16,16), double-buffered.
// ---------------------------------------------------------------------------
__global__ void __launch_bounds__(128) proj_kernel(const float* __restrict__ Wu,
                                                   const float* __restrict__ bu,
                                                   float* __restrict__ out)
{
    __shared__ float As[2][32][68];   // [buf][k][r]
    __shared__ float Bs[2][32][36];   // [buf][k][c]
    const int r0  = blockIdx.x * 64;
    const int c0  = blockIdx.y * 32;
    const int tid = threadIdx.x;
    const int ty  = tid >> 3;       // 0..15 -> rows ty*4..+3
    const int tx  = tid & 7;        // 0..7  -> cols tx*4..+3

    const int ar = tid >> 3;
    const int ak = (tid & 7) * 4;
    const int br = tid >> 3;
    const int bk = (tid & 7) * 4;

    float4 pa[4], pb[2];

    #pragma unroll
    for (int i = 0; i < 4; i++)
        pa[i] = *(const float4*)&g_vec[(size_t)(r0 + ar + i*16)*Ev + ak];
    #pragma unroll
    for (int i = 0; i < 2; i++)
        pb[i] = *(const float4*)&Wu[(size_t)(c0 + br + i*16)*Ev + bk];

    #pragma unroll
    for (int i = 0; i < 4; i++) {
        const int r = ar + i*16;
        As[0][ak][r] = pa[i].x; As[0][ak+1][r] = pa[i].y;
        As[0][ak+2][r] = pa[i].z; As[0][ak+3][r] = pa[i].w;
    }
    #pragma unroll
    for (int i = 0; i < 2; i++) {
        const int c = br + i*16;
        Bs[0][bk][c] = pb[i].x; Bs[0][bk+1][c] = pb[i].y;
        Bs[0][bk+2][c] = pb[i].z; Bs[0][bk+3][c] = pb[i].w;
    }
    __syncthreads();

    u64 accp[4][2];
    #pragma unroll
    for (int r = 0; r < 4; r++) { accp[r][0] = pk2(0.f,0.f); accp[r][1] = pk2(0.f,0.f); }

    for (int t = 0; t < 16; t++) {
        const int cur = t & 1, nxt = cur ^ 1;

        if (t < 15) {
            const int k0 = (t + 1) * 32;
            #pragma unroll
            for (int i = 0; i < 4; i++)
                pa[i] = *(const float4*)&g_vec[(size_t)(r0 + ar + i*16)*Ev + k0 + ak];
            #pragma unroll
            for (int i = 0; i < 2; i++)
                pb[i] = *(const float4*)&Wu[(size_t)(c0 + br + i*16)*Ev + k0 + bk];
        }

        #pragma unroll 8
        for (int k = 0; k < 32; k++) {
            const float4 a4 = *(const float4*)&As[cur][k][ty*4];
            const float4 b4 = *(const float4*)&Bs[cur][k][tx*4];
            const u64 b01 = pk2(b4.x, b4.y), b23 = pk2(b4.z, b4.w);
            const float a[4] = {a4.x, a4.y, a4.z, a4.w};
            #pragma unroll
            for (int ry = 0; ry < 4; ry++) {
                const u64 aa = pk2(a[ry], a[ry]);
                fma2(accp[ry][0], aa, b01);
                fma2(accp[ry][1], aa, b23);
            }
        }

        if (t < 15) {
            #pragma unroll
            for (int i = 0; i < 4; i++) {
                const int r = ar + i*16;
                As[nxt][ak][r] = pa[i].x; As[nxt][ak+1][r] = pa[i].y;
                As[nxt][ak+2][r] = pa[i].z; As[nxt][ak+3][r] = pa[i].w;
            }
            #pragma unroll
            for (int i = 0; i < 2; i++) {
                const int c = br + i*16;
                Bs[nxt][bk][c] = pb[i].x; Bs[nxt][bk+1][c] = pb[i].y;
                Bs[nxt][bk+2][c] = pb[i].z; Bs[nxt][bk+3][c] = pb[i].w;
            }
            __syncthreads();
        }
    }

    const float4 bias = *(const float4*)&bu[c0 + tx*4];
    #pragma unroll
    for (int ry = 0; ry < 4; ry++) {
        float4 o;
        upk2(accp[ry][0], o.x, o.y);
        upk2(accp[ry][1], o.z, o.w);
        o.x += bias.x; o.y += bias.y; o.z += bias.z; o.w += bias.w;
        *(float4*)&out[(size_t)(r0 + ty*4 + ry)*Ev + c0 + tx*4] = o;
    }
}

// ---------------------------------------------------------------------------
extern "C" void kernel_launch(void* const* d_in, const int* in_sizes, int n_in,
                              void* d_out, int out_size)
{
    const float* x   = (const float*)d_in[0];
    const float* rk  = (const float*)d_in[1];
    const float* rv  = (const float*)d_in[2];
    const int*   msk = (const int*)  d_in[3];
    const float* Wq  = (const float*)d_in[4];
    const float* Wk  = (const float*)d_in[5];
    const float* Wv  = (const float*)d_in[6];
    const float* Wu  = (const float*)d_in[7];
    const float* bu  = (const float*)d_in[8];
    float* out = (float*)d_out;

    qkv_kernel<<<dim3(16, Hv), 256>>>(x, Wq, Wk, Wv);
    attn_kernel<<<Bv*Tv, 256>>>(rk, rv, msk);
    proj_kernel<<<dim3(16, 16), 128>>>(Wu, bu, out);
}